// round 1
// baseline (speedup 1.0000x reference)
#include <cuda_runtime.h>
#include <cuda_bf16.h>

// Problem constants
#define B_SZ   512
#define IN_F   512
#define OUT_F  64
#define KD     16
#define NF     (OUT_F * KD)   // 1024

// Scratch for M laid out [o][b][k]  (64 * 512 * 16 floats = 2 MB)
__device__ float g_M[OUT_F * B_SZ * KD];

// ---------------------------------------------------------------------------
// Kernel A: M = x[512,512] @ T[512,1024], stored transposed to [o][b][k]
// Tile 64(M) x 64(N), K-chunk 16, 256 threads, 4x4 microtile per thread.
// ---------------------------------------------------------------------------
#define TM 64
#define TN 64
#define TK 16

__global__ __launch_bounds__(256) void mbd_gemm_kernel(
    const float* __restrict__ x, const float* __restrict__ T)
{
    __shared__ float xs[TM][TK];       // [m][k]
    __shared__ float Ts[TK][TN];       // [k][n]

    const int tid = threadIdx.x;
    const int tx = tid & 15;           // 0..15  -> n microtile
    const int ty = tid >> 4;           // 0..15  -> m microtile
    const int m0 = blockIdx.y * TM;
    const int n0 = blockIdx.x * TN;
    const int r = ty * 4;              // row within tile
    const int c = tx * 4;              // col within tile

    float acc[4][4];
#pragma unroll
    for (int i = 0; i < 4; i++)
#pragma unroll
        for (int j = 0; j < 4; j++) acc[i][j] = 0.f;

    for (int k0 = 0; k0 < IN_F; k0 += TK) {
        // Load xs: 64x16 = 1024 floats, float4 per thread
        {
            int idx = tid * 4;                 // 0..1020
            int m = idx >> 4;                  // idx/16
            int k = idx & 15;                  // multiple of 4
            float4 v = *(const float4*)&x[(m0 + m) * IN_F + k0 + k];
            *(float4*)&xs[m][k] = v;
        }
        // Load Ts: 16x64 = 1024 floats
        {
            int idx = tid * 4;
            int k = idx >> 6;                  // idx/64
            int n = idx & 63;                  // multiple of 4
            float4 v = *(const float4*)&T[(k0 + k) * NF + n0 + n];
            *(float4*)&Ts[k][n] = v;
        }
        __syncthreads();

#pragma unroll
        for (int kk = 0; kk < TK; kk++) {
            float a0 = xs[r + 0][kk];
            float a1 = xs[r + 1][kk];
            float a2 = xs[r + 2][kk];
            float a3 = xs[r + 3][kk];
            float4 bb = *(const float4*)&Ts[kk][c];
            acc[0][0] += a0 * bb.x; acc[0][1] += a0 * bb.y; acc[0][2] += a0 * bb.z; acc[0][3] += a0 * bb.w;
            acc[1][0] += a1 * bb.x; acc[1][1] += a1 * bb.y; acc[1][2] += a1 * bb.z; acc[1][3] += a1 * bb.w;
            acc[2][0] += a2 * bb.x; acc[2][1] += a2 * bb.y; acc[2][2] += a2 * bb.z; acc[2][3] += a2 * bb.w;
            acc[3][0] += a3 * bb.x; acc[3][1] += a3 * bb.y; acc[3][2] += a3 * bb.z; acc[3][3] += a3 * bb.w;
        }
        __syncthreads();
    }

    // Epilogue: write to g_M[o][b][k].  of = n0+c+jj : the 4 consecutive jj
    // stay inside one o (c is a multiple of 4, 4 | 16) and k%4==0 -> float4.
    const int of = n0 + c;
    const int o  = of >> 4;
    const int k  = of & 15;
#pragma unroll
    for (int ii = 0; ii < 4; ii++) {
        int b = m0 + r + ii;
        float4 v = make_float4(acc[ii][0], acc[ii][1], acc[ii][2], acc[ii][3]);
        *(float4*)&g_M[(o * B_SZ + b) * KD + k] = v;
    }
}

// ---------------------------------------------------------------------------
// Kernel B: per output feature o, S[j] = sum_i exp(-sum_k |M[j,k]-M[i,k]|)
// out[j,o] = w[j] * (S[j] - 1)            (self term exp(0)=1 cancels -w[j])
// grid (64, 4), 128 threads; each thread owns one j; M_o staged in shared.
// ---------------------------------------------------------------------------
__global__ __launch_bounds__(128) void mbd_pairwise_kernel(
    const float* __restrict__ w, float* __restrict__ out)
{
    __shared__ float sM[B_SZ * KD];            // 32 KB

    const int o = blockIdx.x;
    const int j = blockIdx.y * 128 + threadIdx.x;

    // Stage M_o (contiguous 32KB) into shared, float4 coalesced
    {
        const float4* src = (const float4*)(g_M + o * (B_SZ * KD));
        float4* dst = (float4*)sM;
        for (int t = threadIdx.x; t < (B_SZ * KD) / 4; t += 128)
            dst[t] = src[t];
    }
    __syncthreads();

    float mj[KD];
#pragma unroll
    for (int k = 0; k < KD; k++) mj[k] = sM[j * KD + k];

    const float4* s4 = (const float4*)sM;
    float S = 0.f;

#pragma unroll 2
    for (int i = 0; i < B_SZ; i++) {
        float4 v0 = s4[i * 4 + 0];             // warp-uniform -> LDS broadcast
        float4 v1 = s4[i * 4 + 1];
        float4 v2 = s4[i * 4 + 2];
        float4 v3 = s4[i * 4 + 3];
        float n0 = fabsf(mj[0]  - v0.x) + fabsf(mj[1]  - v0.y)
                 + fabsf(mj[2]  - v0.z) + fabsf(mj[3]  - v0.w);
        float n1 = fabsf(mj[4]  - v1.x) + fabsf(mj[5]  - v1.y)
                 + fabsf(mj[6]  - v1.z) + fabsf(mj[7]  - v1.w);
        float n2 = fabsf(mj[8]  - v2.x) + fabsf(mj[9]  - v2.y)
                 + fabsf(mj[10] - v2.z) + fabsf(mj[11] - v2.w);
        float n3 = fabsf(mj[12] - v3.x) + fabsf(mj[13] - v3.y)
                 + fabsf(mj[14] - v3.z) + fabsf(mj[15] - v3.w);
        S += __expf(-((n0 + n1) + (n2 + n3)));
    }

    out[j * OUT_F + o] = w[j] * (S - 1.0f);
}

// ---------------------------------------------------------------------------
extern "C" void kernel_launch(void* const* d_in, const int* in_sizes, int n_in,
                              void* d_out, int out_size)
{
    const float* x = (const float*)d_in[0];   // [512, 512]
    const float* w = (const float*)d_in[1];   // [1, 512]
    const float* T = (const float*)d_in[2];   // [512, 64, 16] == [512, 1024]
    float* out = (float*)d_out;               // [512, 64]

    (void)in_sizes; (void)n_in; (void)out_size;

    mbd_gemm_kernel<<<dim3(NF / TN, B_SZ / TM), 256>>>(x, T);
    mbd_pairwise_kernel<<<dim3(OUT_F, B_SZ / 128), 128>>>(w, out);
}

// round 2
// speedup vs baseline: 1.1314x; 1.1314x over previous
#include <cuda_runtime.h>
#include <cuda_bf16.h>

// Problem constants
#define B_SZ   512
#define IN_F   512
#define OUT_F  64
#define KD     16
#define NF     (OUT_F * KD)   // 1024

typedef unsigned long long u64;

// Scratch for M laid out [o][b][k]  (64 * 512 * 16 floats = 2 MB)
__device__ float g_M[OUT_F * B_SZ * KD];

// ---- packed f32x2 helpers (sm_103a) ---------------------------------------
__device__ __forceinline__ u64 fadd2(u64 a, u64 b) {
    u64 r; asm("add.rn.f32x2 %0, %1, %2;" : "=l"(r) : "l"(a), "l"(b)); return r;
}
__device__ __forceinline__ u64 ffma2(u64 a, u64 b, u64 c) {
    u64 r; asm("fma.rn.f32x2 %0, %1, %2, %3;" : "=l"(r) : "l"(a), "l"(b), "l"(c)); return r;
}
__device__ __forceinline__ u64 fabs2(u64 a) {
    return a & 0x7FFFFFFF7FFFFFFFULL;            // clear both sign bits (alu pipe)
}
__device__ __forceinline__ u64 pack2(float lo, float hi) {
    u64 r; asm("mov.b64 %0, {%1, %2};" : "=l"(r) : "f"(lo), "f"(hi)); return r;
}
__device__ __forceinline__ void unpack2(u64 v, float& lo, float& hi) {
    asm("mov.b64 {%0, %1}, %2;" : "=f"(lo), "=f"(hi) : "l"(v));
}

// ---------------------------------------------------------------------------
// Kernel A: M = x[512,512] @ T[512,1024], stored transposed to [o][b][k]
// Tile 64(M) x 64(N), K-chunk 16, 256 threads, 4x4 microtile, packed FFMA2.
// ---------------------------------------------------------------------------
#define TM 64
#define TN 64
#define TK 16

__global__ __launch_bounds__(256) void mbd_gemm_kernel(
    const float* __restrict__ x, const float* __restrict__ T)
{
    __shared__ float xs[TM][TK];       // [m][k]
    __shared__ float Ts[TK][TN];       // [k][n]

    const int tid = threadIdx.x;
    const int tx = tid & 15;           // n microtile
    const int ty = tid >> 4;           // m microtile
    const int m0 = blockIdx.y * TM;
    const int n0 = blockIdx.x * TN;
    const int r = ty * 4;
    const int c = tx * 4;

    // 4 rows x 2 packed columns (= 4x4 scalar accumulators)
    u64 acc[4][2];
#pragma unroll
    for (int i = 0; i < 4; i++) { acc[i][0] = 0ULL; acc[i][1] = 0ULL; }

    for (int k0 = 0; k0 < IN_F; k0 += TK) {
        {
            int idx = tid * 4;
            int m = idx >> 4;
            int k = idx & 15;
            float4 v = *(const float4*)&x[(m0 + m) * IN_F + k0 + k];
            *(float4*)&xs[m][k] = v;
        }
        {
            int idx = tid * 4;
            int k = idx >> 6;
            int n = idx & 63;
            float4 v = *(const float4*)&T[(k0 + k) * NF + n0 + n];
            *(float4*)&Ts[k][n] = v;
        }
        __syncthreads();

#pragma unroll
        for (int kk = 0; kk < TK; kk++) {
            ulonglong2 bb = *(const ulonglong2*)&Ts[kk][c];   // (b0,b1),(b2,b3)
            u64 a0 = pack2(xs[r + 0][kk], xs[r + 0][kk]);
            u64 a1 = pack2(xs[r + 1][kk], xs[r + 1][kk]);
            u64 a2 = pack2(xs[r + 2][kk], xs[r + 2][kk]);
            u64 a3 = pack2(xs[r + 3][kk], xs[r + 3][kk]);
            acc[0][0] = ffma2(a0, bb.x, acc[0][0]); acc[0][1] = ffma2(a0, bb.y, acc[0][1]);
            acc[1][0] = ffma2(a1, bb.x, acc[1][0]); acc[1][1] = ffma2(a1, bb.y, acc[1][1]);
            acc[2][0] = ffma2(a2, bb.x, acc[2][0]); acc[2][1] = ffma2(a2, bb.y, acc[2][1]);
            acc[3][0] = ffma2(a3, bb.x, acc[3][0]); acc[3][1] = ffma2(a3, bb.y, acc[3][1]);
        }
        __syncthreads();
    }

    // Epilogue: g_M[o][b][k].  of = n0+c : 4 consecutive cols live in one o.
    const int of = n0 + c;
    const int o  = of >> 4;
    const int k  = of & 15;
#pragma unroll
    for (int ii = 0; ii < 4; ii++) {
        int b = m0 + r + ii;
        ulonglong2 v; v.x = acc[ii][0]; v.y = acc[ii][1];   // bitwise == float4
        *(ulonglong2*)&g_M[(o * B_SZ + b) * KD + k] = v;
    }
}

// ---------------------------------------------------------------------------
// Kernel B: per output feature o, S[j] = sum_i exp(-sum_k |M[j,k]-M[i,k]|)
// out[j,o] = w[j] * (S[j] - 1)
// grid (64, 4), 512 threads = 128 j x 4 i-quarters; packed f32x2 inner loop.
// ---------------------------------------------------------------------------
__global__ __launch_bounds__(512, 2) void mbd_pairwise_kernel(
    const float* __restrict__ w, float* __restrict__ out)
{
    __shared__ float sM[B_SZ * KD];            // 32 KB
    __shared__ float red[512];

    const int o   = blockIdx.x;
    const int tid = threadIdx.x;
    const int j   = blockIdx.y * 128 + (tid & 127);
    const int q   = tid >> 7;                  // i-quarter 0..3

    // Stage M_o (contiguous 32KB) into shared, float4 coalesced
    {
        const float4* src = (const float4*)(g_M + o * (B_SZ * KD));
        float4* dst = (float4*)sM;
#pragma unroll
        for (int t = 0; t < 4; t++)
            dst[tid + t * 512] = src[tid + t * 512];
    }
    __syncthreads();

    // Pre-negated packed row j: mjn[p] = (-M[j,2p], -M[j,2p+1])
    u64 mjn[8];
#pragma unroll
    for (int p = 0; p < 8; p++)
        mjn[p] = pack2(-sM[j * KD + 2 * p], -sM[j * KD + 2 * p + 1]);

    const ulonglong2* s2 = (const ulonglong2*)sM;   // 4 x ulonglong2 per row
    float S = 0.f;
    const int i0 = q * 128;

#pragma unroll 2
    for (int i = i0; i < i0 + 128; i++) {
        ulonglong2 v0 = s2[i * 4 + 0];         // warp-uniform -> LDS broadcast
        ulonglong2 v1 = s2[i * 4 + 1];
        ulonglong2 v2 = s2[i * 4 + 2];
        ulonglong2 v3 = s2[i * 4 + 3];
        u64 a0 = fabs2(fadd2(v0.x, mjn[0]));
        u64 a1 = fabs2(fadd2(v0.y, mjn[1]));
        u64 a2 = fabs2(fadd2(v1.x, mjn[2]));
        u64 a3 = fabs2(fadd2(v1.y, mjn[3]));
        u64 a4 = fabs2(fadd2(v2.x, mjn[4]));
        u64 a5 = fabs2(fadd2(v2.y, mjn[5]));
        u64 a6 = fabs2(fadd2(v3.x, mjn[6]));
        u64 a7 = fabs2(fadd2(v3.y, mjn[7]));
        u64 t = fadd2(fadd2(fadd2(a0, a1), fadd2(a2, a3)),
                      fadd2(fadd2(a4, a5), fadd2(a6, a7)));
        float lo, hi; unpack2(t, lo, hi);
        S += __expf(-(lo + hi));
    }

    red[tid] = S;
    __syncthreads();

    if (q == 0) {
        float St = red[tid] + red[tid + 128] + red[tid + 256] + red[tid + 384];
        out[j * OUT_F + o] = w[j] * (St - 1.0f);
    }
}

// ---------------------------------------------------------------------------
extern "C" void kernel_launch(void* const* d_in, const int* in_sizes, int n_in,
                              void* d_out, int out_size)
{
    const float* x = (const float*)d_in[0];   // [512, 512]
    const float* w = (const float*)d_in[1];   // [1, 512]
    const float* T = (const float*)d_in[2];   // [512, 64, 16]
    float* out = (float*)d_out;               // [512, 64]

    (void)in_sizes; (void)n_in; (void)out_size;

    mbd_gemm_kernel<<<dim3(NF / TN, B_SZ / TM), 256>>>(x, T);
    mbd_pairwise_kernel<<<dim3(OUT_F, 4), 512>>>(w, out);
}